// round 1
// baseline (speedup 1.0000x reference)
#include <cuda_runtime.h>
#include <cuda_bf16.h>
#include <math.h>

// Problem constants
#define NN      8192
#define SS      4
#define BB      2
#define EE      262144          // edges per relation (2^18)
#define TOTE    (SS*EE)         // 1048576 total edges
#define HH      64
#define FF      32
#define CC      2

// ---------------- device scratch (statically reserved; no runtime alloc) ---------
__device__ float g_Wcat1[NN*128];                 // 4 MB   [k][b*64+h]
__device__ float g_part [4*NN*128];               // 16 MB  split-K partials
__device__ float g_sup1 [SS*NN*HH];               // 8 MB   [s][n][64]
__device__ float g_X1   [NN*HH];                  // 2 MB
__device__ float g_Wcat2[64*64];                  // [k][b*32+f]
__device__ float g_U2   [NN*64];                  // 2 MB
__device__ float g_sup2 [SS*NN*FF];               // 4 MB
__device__ int   g_deg  [NN];
__device__ int   g_rowptr[NN+1];
__device__ int   g_cursor[NN];
__device__ int   g_gidx [TOTE];                   // s*NN + src, sorted by dst
__device__ float g_ew   [TOTE];

// ---------------- CSR construction ----------------------------------------------
__global__ void zero_counts_kernel() {
    int i = blockIdx.x*256 + threadIdx.x;
    if (i < NN) { g_deg[i] = 0; g_cursor[i] = 0; }
}

__global__ void hist_kernel(const int* __restrict__ dst) {
    int i = blockIdx.x*256 + threadIdx.x;
    if (i < TOTE) atomicAdd(&g_deg[dst[i]], 1);
}

// single block: exclusive scan of 8192 degrees
__global__ void scan_kernel() {
    __shared__ int part[1024];
    int t = threadIdx.x;
    int base = t*8;
    int local[8]; int s = 0;
    #pragma unroll
    for (int i=0;i<8;i++){ local[i] = s; s += g_deg[base+i]; }
    part[t] = s;
    __syncthreads();
    for (int off=1; off<1024; off<<=1) {
        int v = (t >= off) ? part[t-off] : 0;
        __syncthreads();
        part[t] += v;
        __syncthreads();
    }
    int pre = (t==0) ? 0 : part[t-1];
    #pragma unroll
    for (int i=0;i<8;i++) g_rowptr[base+i] = pre + local[i];
    if (t == 1023) g_rowptr[NN] = part[1023];
}

__global__ void scatter_kernel(const int* __restrict__ src,
                               const int* __restrict__ dst,
                               const float* __restrict__ w) {
    int i = blockIdx.x*256 + threadIdx.x;
    if (i >= TOTE) return;
    int s = i >> 18;                         // E = 2^18
    int d = dst[i];
    int p = g_rowptr[d] + atomicAdd(&g_cursor[d], 1);
    g_gidx[p] = s*NN + src[i];
    g_ew[p]   = w[i];
}

// ---------------- weight repack --------------------------------------------------
__global__ void repack1_kernel(const float* __restrict__ W1) {
    int i = blockIdx.x*256 + threadIdx.x;    // over 2*8192*64
    if (i >= BB*NN*HH) return;
    int b = i / (NN*HH);
    int r = i % (NN*HH);
    int k = r / HH, h = r % HH;
    g_Wcat1[k*128 + b*64 + h] = W1[i];
}

__global__ void repack2_kernel(const float* __restrict__ W2) {
    int i = blockIdx.x*256 + threadIdx.x;    // over 2*64*32
    if (i >= BB*64*FF) return;
    int b = i / (64*FF);
    int r = i % (64*FF);
    int k = r / FF, f = r % FF;
    g_Wcat2[k*64 + b*32 + f] = W2[i];
}

// ---------------- GEMM1: feat[8192,8192] @ Wcat1[8192,128] (split-K=4) -----------
// 128x128 tile, BK=8, 256 threads, 8x8 per thread.
__global__ void __launch_bounds__(256, 2)
gemm1_kernel(const float* __restrict__ A) {
    const int K = NN;
    __shared__ float As[8][132];
    __shared__ float Bs[8][128];
    int mblk  = blockIdx.x;      // 0..63
    int split = blockIdx.y;      // 0..3
    int k0    = split * 2048;
    int tid   = threadIdx.x;
    int tm0   = (tid >> 4) * 8;  // 16x16 thread grid
    int tn0   = (tid & 15) * 8;

    float acc[8][8];
    #pragma unroll
    for (int i=0;i<8;i++)
        #pragma unroll
        for (int j=0;j<8;j++) acc[i][j] = 0.f;

    const float* Ablk = A + (size_t)(mblk*128)*K;
    int ar  = tid >> 1;          // 0..127
    int ac4 = (tid & 1) * 4;     // 0 or 4
    int br  = tid >> 5;          // 0..7
    int bc  = (tid & 31) * 4;

    for (int kt = 0; kt < 2048; kt += 8) {
        float4 va = *(const float4*)(Ablk + (size_t)ar*K + (k0 + kt + ac4));
        As[ac4+0][ar] = va.x; As[ac4+1][ar] = va.y;
        As[ac4+2][ar] = va.z; As[ac4+3][ar] = va.w;
        *(float4*)&Bs[br][bc] =
            *(const float4*)(g_Wcat1 + (size_t)(k0 + kt + br)*128 + bc);
        __syncthreads();
        #pragma unroll
        for (int k=0;k<8;k++) {
            float ra[8], rb[8];
            #pragma unroll
            for (int i=0;i<8;i++) ra[i] = As[k][tm0+i];
            #pragma unroll
            for (int j=0;j<8;j++) rb[j] = Bs[k][tn0+j];
            #pragma unroll
            for (int i=0;i<8;i++)
                #pragma unroll
                for (int j=0;j<8;j++) acc[i][j] += ra[i]*rb[j];
        }
        __syncthreads();
    }
    float* C = g_part + (size_t)split*NN*128 + (size_t)(mblk*128)*128;
    #pragma unroll
    for (int i=0;i<8;i++)
        #pragma unroll
        for (int j=0;j<8;j+=4)
            *(float4*)&C[(size_t)(tm0+i)*128 + tn0 + j] =
                make_float4(acc[i][j],acc[i][j+1],acc[i][j+2],acc[i][j+3]);
}

// ---------------- fused split-K reduce + basis combine (layer 1) ------------------
// sup1[s][n][h] = Wc1[s,0]*U[n][h] + Wc1[s,1]*U[n][64+h],  U = sum of 4 partials
__global__ void combine1_kernel(const float* __restrict__ Wc1) {
    int i = blockIdx.x*256 + threadIdx.x;   // over 8192*64
    if (i >= NN*HH) return;
    int n = i >> 6, h = i & 63;
    const int sz = NN*128;
    int i0 = n*128 + h, i1 = n*128 + 64 + h;
    float u0 = g_part[i0] + g_part[sz+i0] + g_part[2*sz+i0] + g_part[3*sz+i0];
    float u1 = g_part[i1] + g_part[sz+i1] + g_part[2*sz+i1] + g_part[3*sz+i1];
    #pragma unroll
    for (int s=0;s<4;s++)
        g_sup1[((size_t)s*NN + n)*HH + h] = Wc1[2*s]*u0 + Wc1[2*s+1]*u1;
}

// ---------------- aggregation layer 1: warp per dst, 64-wide, tanh ----------------
__global__ void agg1_kernel() {
    int warp = (blockIdx.x*blockDim.x + threadIdx.x) >> 5;
    int lane = threadIdx.x & 31;
    if (warp >= NN) return;
    int beg = g_rowptr[warp], end = g_rowptr[warp+1];
    float ax = 0.f, ay = 0.f;
    int e = beg;
    for (; e + 3 < end; e += 4) {
        int   g0 = g_gidx[e],   g1 = g_gidx[e+1], g2 = g_gidx[e+2], g3 = g_gidx[e+3];
        float w0 = g_ew[e],     w1 = g_ew[e+1],   w2 = g_ew[e+2],   w3 = g_ew[e+3];
        float2 v0 = *(const float2*)(g_sup1 + (size_t)g0*64 + 2*lane);
        float2 v1 = *(const float2*)(g_sup1 + (size_t)g1*64 + 2*lane);
        float2 v2 = *(const float2*)(g_sup1 + (size_t)g2*64 + 2*lane);
        float2 v3 = *(const float2*)(g_sup1 + (size_t)g3*64 + 2*lane);
        ax += w0*v0.x + w1*v1.x + w2*v2.x + w3*v3.x;
        ay += w0*v0.y + w1*v1.y + w2*v2.y + w3*v3.y;
    }
    for (; e < end; e++) {
        int g = g_gidx[e]; float w = g_ew[e];
        float2 v = *(const float2*)(g_sup1 + (size_t)g*64 + 2*lane);
        ax += w*v.x; ay += w*v.y;
    }
    float2 o; o.x = tanhf(ax); o.y = tanhf(ay);
    *(float2*)(g_X1 + (size_t)warp*64 + 2*lane) = o;
}

// ---------------- GEMM2: X1[8192,64] @ Wcat2[64,64] -------------------------------
__global__ void gemm2_kernel() {
    __shared__ float Ws[64][64];
    __shared__ float Xs[64][65];
    int tid = threadIdx.x;
    for (int i = tid; i < 4096; i += 256) Ws[i>>6][i&63] = g_Wcat2[i];
    int row0 = blockIdx.x * 64;
    for (int i = tid; i < 4096; i += 256)
        Xs[i>>6][i&63] = g_X1[(size_t)(row0 + (i>>6))*64 + (i&63)];
    __syncthreads();
    int r  = tid >> 2;
    int c0 = (tid & 3) * 16;
    float acc[16];
    #pragma unroll
    for (int j=0;j<16;j++) acc[j] = 0.f;
    #pragma unroll 8
    for (int k=0;k<64;k++) {
        float x = Xs[r][k];
        #pragma unroll
        for (int j=0;j<16;j++) acc[j] += x * Ws[k][c0+j];
    }
    #pragma unroll
    for (int j=0;j<16;j++) g_U2[(size_t)(row0+r)*64 + c0 + j] = acc[j];
}

// ---------------- basis combine layer 2 ------------------------------------------
__global__ void combine2_kernel(const float* __restrict__ Wc2) {
    int i = blockIdx.x*256 + threadIdx.x;   // over 8192*32
    if (i >= NN*FF) return;
    int n = i >> 5, f = i & 31;
    float u0 = g_U2[n*64 + f];
    float u1 = g_U2[n*64 + 32 + f];
    #pragma unroll
    for (int s=0;s<4;s++)
        g_sup2[((size_t)s*NN + n)*FF + f] = Wc2[2*s]*u0 + Wc2[2*s+1]*u1;
}

// ---------------- aggregation layer 2 + tanh + classifier -------------------------
__global__ void agg2_kernel(const float* __restrict__ Wclf,
                            const float* __restrict__ bclf,
                            float* __restrict__ out) {
    int warp = (blockIdx.x*blockDim.x + threadIdx.x) >> 5;
    int lane = threadIdx.x & 31;
    if (warp >= NN) return;
    int beg = g_rowptr[warp], end = g_rowptr[warp+1];
    float acc = 0.f;
    int e = beg;
    for (; e + 3 < end; e += 4) {
        int   g0 = g_gidx[e],   g1 = g_gidx[e+1], g2 = g_gidx[e+2], g3 = g_gidx[e+3];
        float w0 = g_ew[e],     w1 = g_ew[e+1],   w2 = g_ew[e+2],   w3 = g_ew[e+3];
        acc += w0 * g_sup2[(size_t)g0*32 + lane];
        acc += w1 * g_sup2[(size_t)g1*32 + lane];
        acc += w2 * g_sup2[(size_t)g2*32 + lane];
        acc += w3 * g_sup2[(size_t)g3*32 + lane];
    }
    for (; e < end; e++)
        acc += g_ew[e] * g_sup2[(size_t)g_gidx[e]*32 + lane];
    float x = tanhf(acc);
    float p0 = x * Wclf[lane*2 + 0];
    float p1 = x * Wclf[lane*2 + 1];
    #pragma unroll
    for (int off=16; off; off >>= 1) {
        p0 += __shfl_down_sync(0xFFFFFFFFu, p0, off);
        p1 += __shfl_down_sync(0xFFFFFFFFu, p1, off);
    }
    if (lane == 0) {
        out[warp*2 + 0] = p0 + bclf[0];
        out[warp*2 + 1] = p1 + bclf[1];
    }
}

// ---------------- launch ----------------------------------------------------------
extern "C" void kernel_launch(void* const* d_in, const int* in_sizes, int n_in,
                              void* d_out, int out_size) {
    const float* feat   = (const float*)d_in[0];
    const float* edge_w = (const float*)d_in[1];
    const float* W1     = (const float*)d_in[2];
    const float* Wc1    = (const float*)d_in[3];
    const float* W2     = (const float*)d_in[4];
    const float* Wc2    = (const float*)d_in[5];
    const float* Wclf   = (const float*)d_in[6];
    const float* bclf   = (const float*)d_in[7];
    const int*   esrc   = (const int*)d_in[8];
    const int*   edst   = (const int*)d_in[9];
    float* out = (float*)d_out;

    // CSR build (shared by both layers)
    zero_counts_kernel<<<(NN+255)/256, 256>>>();
    hist_kernel<<<(TOTE+255)/256, 256>>>(edst);
    scan_kernel<<<1, 1024>>>();
    scatter_kernel<<<(TOTE+255)/256, 256>>>(esrc, edst, edge_w);

    // layer 1
    repack1_kernel<<<(BB*NN*HH+255)/256, 256>>>(W1);
    gemm1_kernel<<<dim3(64,4), 256>>>(feat);
    combine1_kernel<<<(NN*HH+255)/256, 256>>>(Wc1);
    agg1_kernel<<<NN/8, 256>>>();

    // layer 2
    repack2_kernel<<<(BB*64*FF+255)/256, 256>>>(W2);
    gemm2_kernel<<<NN/64, 256>>>();
    combine2_kernel<<<(NN*FF+255)/256, 256>>>(Wc2);

    // layer 2 aggregation + classifier fused
    agg2_kernel<<<NN/8, 256>>>(Wclf, bclf, out);
}

// round 14
// speedup vs baseline: 1.3082x; 1.3082x over previous
#include <cuda_runtime.h>
#include <cuda_bf16.h>
#include <stdint.h>
#include <math.h>

// Problem constants
#define NN      8192
#define SS      4
#define BB      2
#define EE      262144          // edges per relation (2^18)
#define TOTE    (SS*EE)         // 1048576 total edges
#define HH      64
#define FF      32
#define CC      2

// ---------------- device scratch (statically reserved; no runtime alloc) ---------
__device__ float g_Wcat1h[NN*128];                // 4 MB   [k][b*64+h], tf32 hi
__device__ float g_Wcat1l[NN*128];                // 4 MB   tf32 lo residual
__device__ float g_U1   [NN*128];                 // 4 MB   feat @ Wcat1
__device__ float g_sup1 [SS*NN*HH];               // 8 MB   [s][n][64]
__device__ float g_X1   [NN*HH];                  // 2 MB
__device__ float g_Wcat2[64*64];                  // [k][b*32+f]
__device__ float g_U2   [NN*64];                  // 2 MB
__device__ float g_sup2 [SS*NN*FF];               // 4 MB
__device__ int   g_deg  [NN];
__device__ int   g_rowptr[NN+1];
__device__ int   g_cursor[NN];
__device__ int   g_gidx [TOTE];                   // s*NN + src, sorted by dst
__device__ float g_ew   [TOTE];

__device__ __forceinline__ float to_tf32(float x) {
    float r;
    asm("cvt.rna.tf32.f32 %0, %1;" : "=f"(r) : "f"(x));
    return r;
}
__device__ __forceinline__ void split_tf32(float x, float& h, float& l) {
    h = to_tf32(x);
    l = to_tf32(x - h);
}

// ---------------- CSR construction ----------------------------------------------
__global__ void zero_counts_kernel() {
    int i = blockIdx.x*256 + threadIdx.x;
    if (i < NN) { g_deg[i] = 0; g_cursor[i] = 0; }
}

__global__ void hist_kernel(const int* __restrict__ dst) {
    int i = blockIdx.x*256 + threadIdx.x;
    if (i < TOTE) atomicAdd(&g_deg[dst[i]], 1);
}

// single block: exclusive scan of 8192 degrees
__global__ void scan_kernel() {
    __shared__ int part[1024];
    int t = threadIdx.x;
    int base = t*8;
    int local[8]; int s = 0;
    #pragma unroll
    for (int i=0;i<8;i++){ local[i] = s; s += g_deg[base+i]; }
    part[t] = s;
    __syncthreads();
    for (int off=1; off<1024; off<<=1) {
        int v = (t >= off) ? part[t-off] : 0;
        __syncthreads();
        part[t] += v;
        __syncthreads();
    }
    int pre = (t==0) ? 0 : part[t-1];
    #pragma unroll
    for (int i=0;i<8;i++) g_rowptr[base+i] = pre + local[i];
    if (t == 1023) g_rowptr[NN] = part[1023];
}

__global__ void scatter_kernel(const int* __restrict__ src,
                               const int* __restrict__ dst,
                               const float* __restrict__ w) {
    int i = blockIdx.x*256 + threadIdx.x;
    if (i >= TOTE) return;
    int s = i >> 18;                         // E = 2^18
    int d = dst[i];
    int p = g_rowptr[d] + atomicAdd(&g_cursor[d], 1);
    g_gidx[p] = s*NN + src[i];
    g_ew[p]   = w[i];
}

// ---------------- weight repack: tf32 hi/lo split of B ---------------------------
__global__ void repack1_kernel(const float* __restrict__ W1) {
    int i = blockIdx.x*256 + threadIdx.x;    // over 2*8192*64
    if (i >= BB*NN*HH) return;
    int b = i / (NN*HH);
    int r = i % (NN*HH);
    int k = r / HH, h = r % HH;
    float hi, lo;
    split_tf32(W1[i], hi, lo);
    g_Wcat1h[k*128 + b*64 + h] = hi;
    g_Wcat1l[k*128 + b*64 + h] = lo;
}

__global__ void repack2_kernel(const float* __restrict__ W2) {
    int i = blockIdx.x*256 + threadIdx.x;    // over 2*64*32
    if (i >= BB*64*FF) return;
    int b = i / (64*FF);
    int r = i % (64*FF);
    int k = r / FF, f = r % FF;
    g_Wcat2[k*64 + b*32 + f] = W2[i];
}

// ---------------- GEMM1: feat[8192,8192] @ Wcat1[8192,128], 3-pass tf32 ----------
// acc += Ah*Bh + Al*Bh + Ah*Bl  (drops Al*Bl ~ eps^2 ~ 8e-8 relative)
// Tile: BM=64, BN=128, BK=32. 256 threads = 8 warps (2x4), warp tile 32x32.
// Smem (dynamic, double buffered): Ah/Al [2][64][36], Bh/Bl [2][32][136]
#define G1_BM 64
#define G1_BK 32
#define AS_PAD 36
#define BS_PAD 136
#define AS_STAGE (G1_BM*AS_PAD)     // 2304 floats
#define BS_STAGE (G1_BK*BS_PAD)     // 4352 floats
#define AH_OFF 0
#define AL_OFF (2*AS_STAGE)
#define BH_OFF (4*AS_STAGE)
#define BL_OFF (4*AS_STAGE + 2*BS_STAGE)
#define G1_SMEM_FLOATS (4*AS_STAGE + 4*BS_STAGE)   // 26624 floats = 106496 B

__device__ __forceinline__ void cp_async16(uint32_t smem_addr, const void* gptr) {
    asm volatile("cp.async.cg.shared.global [%0], [%1], 16;\n"
                 :: "r"(smem_addr), "l"(gptr));
}

#define MMA_TF32(ACC, AF, BF)                                              \
    asm volatile(                                                          \
        "mma.sync.aligned.m16n8k8.row.col.f32.tf32.tf32.f32 "              \
        "{%0,%1,%2,%3}, {%4,%5,%6,%7}, {%8,%9}, {%0,%1,%2,%3};"            \
        : "+f"((ACC)[0]), "+f"((ACC)[1]), "+f"((ACC)[2]), "+f"((ACC)[3])   \
        : "r"((AF)[0]), "r"((AF)[1]), "r"((AF)[2]), "r"((AF)[3]),          \
          "r"((BF)[0]), "r"((BF)[1]))

__global__ void __launch_bounds__(256, 1)
gemm1_kernel(const float* __restrict__ A) {
    extern __shared__ float sm[];

    const int tid  = threadIdx.x;
    const int warp = tid >> 5;
    const int lane = tid & 31;
    const int wm   = warp >> 2;           // 0..1
    const int wn   = warp & 3;            // 0..3
    const int g    = lane >> 2;           // group 0..7
    const int tg   = lane & 3;            // 0..3
    const int m0   = blockIdx.x * G1_BM;

    // staging maps
    const int arow = tid >> 2;            // 0..63
    const int af4  = tid & 3;             // 0..3  (handles float4 slots af4 and af4+4)
    const float* Arow_base = A + (size_t)(m0 + arow) * NN;

    float acc[2][4][4];
    #pragma unroll
    for (int i=0;i<2;i++)
        #pragma unroll
        for (int j=0;j<4;j++)
            #pragma unroll
            for (int c=0;c<4;c++) acc[i][j][c] = 0.f;

    // ---- helper lambda-ish A staging (manual) ----
    // ---- prologue: fill stage 0 ----
    {
        float4 va0 = *(const float4*)(Arow_base + af4*4);
        float4 va1 = *(const float4*)(Arow_base + af4*4 + 16);
        float* dh0 = sm + AH_OFF + arow*AS_PAD + af4*4;
        float* dl0 = sm + AL_OFF + arow*AS_PAD + af4*4;
        float h, l;
        split_tf32(va0.x,h,l); dh0[0]=h; dl0[0]=l;
        split_tf32(va0.y,h,l); dh0[1]=h; dl0[1]=l;
        split_tf32(va0.z,h,l); dh0[2]=h; dl0[2]=l;
        split_tf32(va0.w,h,l); dh0[3]=h; dl0[3]=l;
        split_tf32(va1.x,h,l); dh0[16]=h; dl0[16]=l;
        split_tf32(va1.y,h,l); dh0[17]=h; dl0[17]=l;
        split_tf32(va1.z,h,l); dh0[18]=h; dl0[18]=l;
        split_tf32(va1.w,h,l); dh0[19]=h; dl0[19]=l;
        #pragma unroll
        for (int i=0;i<4;i++) {
            int idx = tid + 256*i;          // 0..1023 float4s of B tile
            int br = idx >> 5, q = idx & 31;
            uint32_t dh = (uint32_t)__cvta_generic_to_shared(sm + BH_OFF + br*BS_PAD + q*4);
            cp_async16(dh, g_Wcat1h + (size_t)br*128 + q*4);
            uint32_t dl = (uint32_t)__cvta_generic_to_shared(sm + BL_OFF + br*BS_PAD + q*4);
            cp_async16(dl, g_Wcat1l + (size_t)br*128 + q*4);
        }
        asm volatile("cp.async.commit_group;");
        asm volatile("cp.async.wait_group 0;");
    }
    __syncthreads();

    #pragma unroll 1
    for (int kt = 0; kt < NN; kt += G1_BK) {
        const int s = (kt >> 5) & 1;
        const bool has_next = (kt + G1_BK) < NN;
        float4 pa0, pa1;
        if (has_next) {
            const int knx = kt + G1_BK;
            #pragma unroll
            for (int i=0;i<4;i++) {
                int idx = tid + 256*i;
                int br = idx >> 5, q = idx & 31;
                uint32_t dh = (uint32_t)__cvta_generic_to_shared(
                    sm + BH_OFF + (s^1)*BS_STAGE + br*BS_PAD + q*4);
                cp_async16(dh, g_Wcat1h + (size_t)(knx + br)*128 + q*4);
                uint32_t dl = (uint32_t)__cvta_generic_to_shared(
                    sm + BL_OFF + (s^1)*BS_STAGE + br*BS_PAD + q*4);
                cp_async16(dl, g_Wcat1l + (size_t)(knx + br)*128 + q*4);
            }
            asm volatile("cp.async.commit_group;");
            pa0 = *(const float4*)(Arow_base + knx + af4*4);
            pa1 = *(const float4*)(Arow_base + knx + af4*4 + 16);
        }

        // ---- compute on stage s ----
        const float* Ahc = sm + AH_OFF + s*AS_STAGE;
        const float* Alc = sm + AL_OFF + s*AS_STAGE;
        const float* Bhc = sm + BH_OFF + s*BS_STAGE;
        const float* Blc = sm + BL_OFF + s*BS_STAGE;
        #pragma unroll
        for (int kc = 0; kc < 4; kc++) {
            uint32_t afh[2][4], afl[2][4];
            #pragma unroll
            for (int i=0;i<2;i++) {
                int off = (wm*32 + i*16 + g)*AS_PAD + kc*8 + tg;
                const float* ph = Ahc + off;
                afh[i][0] = __float_as_uint(ph[0]);
                afh[i][1] = __float_as_uint(ph[8*AS_PAD]);
                afh[i][2] = __float_as_uint(ph[4]);
                afh[i][3] = __float_as_uint(ph[8*AS_PAD + 4]);
                const float* pl = Alc + off;
                afl[i][0] = __float_as_uint(pl[0]);
                afl[i][1] = __float_as_uint(pl[8*AS_PAD]);
                afl[i][2] = __float_as_uint(pl[4]);
                afl[i][3] = __float_as_uint(pl[8*AS_PAD + 4]);
            }
            uint32_t bfh[4][2], bfl[4][2];
            #pragma unroll
            for (int j=0;j<4;j++) {
                int off = (kc*8 + tg)*BS_PAD + wn*32 + j*8 + g;
                const float* ph = Bhc + off;
                bfh[j][0] = __float_as_uint(ph[0]);
                bfh[j][1] = __float_as_uint(ph[4*BS_PAD]);
                const float* pl = Blc + off;
                bfl[j][0] = __float_as_uint(pl[0]);
                bfl[j][1] = __float_as_uint(pl[4*BS_PAD]);
            }
            #pragma unroll
            for (int i=0;i<2;i++)
                #pragma unroll
                for (int j=0;j<4;j++) {
                    MMA_TF32(acc[i][j], afh[i], bfh[j]);   // Ah*Bh
                    MMA_TF32(acc[i][j], afl[i], bfh[j]);   // Al*Bh
                    MMA_TF32(acc[i][j], afh[i], bfl[j]);   // Ah*Bl
                }
        }

        if (has_next) {
            float* dh0 = sm + AH_OFF + (s^1)*AS_STAGE + arow*AS_PAD + af4*4;
            float* dl0 = sm + AL_OFF + (s^1)*AS_STAGE + arow*AS_PAD + af4*4;
            float h, l;
            split_tf32(pa0.x,h,l); dh0[0]=h; dl0[0]=l;
            split_tf32(pa0.y,h,l); dh0[1]=h; dl0[1]=l;
            split_tf32(pa0.z,h,l); dh0[2]=h; dl0[2]=l;
            split_tf32(pa0.w,h,l); dh0[3]=h; dl0[3]=l;
            split_tf32(pa1.x,h,l); dh0[16]=h; dl0[16]=l;
            split_tf32(pa1.y,h,l); dh0[17]=h; dl0[17]=l;
            split_tf32(pa1.z,h,l); dh0[18]=h; dl0[18]=l;
            split_tf32(pa1.w,h,l); dh0[19]=h; dl0[19]=l;
            asm volatile("cp.async.wait_group 0;");
        }
        __syncthreads();
    }

    // ---- writeback ----
    #pragma unroll
    for (int i=0;i<2;i++) {
        int row = m0 + wm*32 + i*16 + g;
        #pragma unroll
        for (int j=0;j<4;j++) {
            int col = wn*32 + j*8 + 2*tg;
            *(float2*)(g_U1 + (size_t)row*128 + col) =
                make_float2(acc[i][j][0], acc[i][j][1]);
            *(float2*)(g_U1 + (size_t)(row+8)*128 + col) =
                make_float2(acc[i][j][2], acc[i][j][3]);
        }
    }
}

// ---------------- basis combine (layer 1) ----------------------------------------
// sup1[s][n][h] = Wc1[s,0]*U[n][h] + Wc1[s,1]*U[n][64+h]
__global__ void combine1_kernel(const float* __restrict__ Wc1) {
    int i = blockIdx.x*256 + threadIdx.x;   // over 8192*64
    if (i >= NN*HH) return;
    int n = i >> 6, h = i & 63;
    float u0 = g_U1[n*128 + h];
    float u1 = g_U1[n*128 + 64 + h];
    #pragma unroll
    for (int s=0;s<4;s++)
        g_sup1[((size_t)s*NN + n)*HH + h] = Wc1[2*s]*u0 + Wc1[2*s+1]*u1;
}

// ---------------- aggregation layer 1: warp per dst, 64-wide, tanh ----------------
__global__ void agg1_kernel() {
    int warp = (blockIdx.x*blockDim.x + threadIdx.x) >> 5;
    int lane = threadIdx.x & 31;
    if (warp >= NN) return;
    int beg = g_rowptr[warp], end = g_rowptr[warp+1];
    float ax = 0.f, ay = 0.f;
    int e = beg;
    for (; e + 3 < end; e += 4) {
        int   g0 = g_gidx[e],   g1 = g_gidx[e+1], g2 = g_gidx[e+2], g3 = g_gidx[e+3];
        float w0 = g_ew[e],     w1 = g_ew[e+1],   w2 = g_ew[e+2],   w3 = g_ew[e+3];
        float2 v0 = *(const float2*)(g_sup1 + (size_t)g0*64 + 2*lane);
        float2 v1 = *(const float2*)(g_sup1 + (size_t)g1*64 + 2*lane);
        float2 v2 = *(const float2*)(g_sup1 + (size_t)g2*64 + 2*lane);
        float2 v3 = *(const float2*)(g_sup1 + (size_t)g3*64 + 2*lane);
        ax += w0*v0.x + w1*v1.x + w2*v2.x + w3*v3.x;
        ay += w0*v0.y + w1*v1.y + w2*v2.y + w3*v3.y;
    }
    for (; e < end; e++) {
        int g = g_gidx[e]; float w = g_ew[e];
        float2 v = *(const float2*)(g_sup1 + (size_t)g*64 + 2*lane);
        ax += w*v.x; ay += w*v.y;
    }
    float2 o; o.x = tanhf(ax); o.y = tanhf(ay);
    *(float2*)(g_X1 + (size_t)warp*64 + 2*lane) = o;
}

// ---------------- GEMM2: X1[8192,64] @ Wcat2[64,64] -------------------------------
__global__ void gemm2_kernel() {
    __shared__ float Ws[64][64];
    __shared__ float Xs[64][65];
    int tid = threadIdx.x;
    for (int i = tid; i < 4096; i += 256) Ws[i>>6][i&63] = g_Wcat2[i];
    int row0 = blockIdx.x * 64;
    for (int i = tid; i < 4096; i += 256)
        Xs[i>>6][i&63] = g_X1[(size_t)(row0 + (i>>6))*64 + (i&63)];
    __syncthreads();
    int r  = tid >> 2;
    int c0 = (tid & 3) * 16;
    float acc[16];
    #pragma unroll
    for (int j=0;j<16;j++) acc[j] = 0.f;
    #pragma unroll 8
    for (int k=0;k<64;k++) {
        float x = Xs[r][k];
        #pragma unroll
        for (int j=0;j<16;j++) acc[j] += x * Ws[k][c0+j];
    }
    #pragma unroll
    for (int j=0;j<16;j++) g_U2[(size_t)(row0+r)*64 + c0 + j] = acc[j];
}

// ---------------- basis combine layer 2 ------------------------------------------
__global__ void combine2_kernel(const float* __restrict__ Wc2) {
    int i = blockIdx.x*256 + threadIdx.x;   // over 8192*32
    if (i >= NN*FF) return;
    int n = i >> 5, f = i & 31;
    float u0 = g_U2[n*64 + f];
    float u1 = g_U2[n*64 + 32 + f];
    #pragma unroll
    for (int s=0;s<4;s++)
        g_sup2[((size_t)s*NN + n)*FF + f] = Wc2[2*s]*u0 + Wc2[2*s+1]*u1;
}

// ---------------- aggregation layer 2 + tanh + classifier -------------------------
__global__ void agg2_kernel(const float* __restrict__ Wclf,
                            const float* __restrict__ bclf,
                            float* __restrict__ out) {
    int warp = (blockIdx.x*blockDim.x + threadIdx.x) >> 5;
    int lane = threadIdx.x & 31;
    if (warp >= NN) return;
    int beg = g_rowptr[warp], end = g_rowptr[warp+1];
    float acc = 0.f;
    int e = beg;
    for (; e + 3 < end; e += 4) {
        int   g0 = g_gidx[e],   g1 = g_gidx[e+1], g2 = g_gidx[e+2], g3 = g_gidx[e+3];
        float w0 = g_ew[e],     w1 = g_ew[e+1],   w2 = g_ew[e+2],   w3 = g_ew[e+3];
        acc += w0 * g_sup2[(size_t)g0*32 + lane];
        acc += w1 * g_sup2[(size_t)g1*32 + lane];
        acc += w2 * g_sup2[(size_t)g2*32 + lane];
        acc += w3 * g_sup2[(size_t)g3*32 + lane];
    }
    for (; e < end; e++)
        acc += g_ew[e] * g_sup2[(size_t)g_gidx[e]*32 + lane];
    float x = tanhf(acc);
    float p0 = x * Wclf[lane*2 + 0];
    float p1 = x * Wclf[lane*2 + 1];
    #pragma unroll
    for (int off=16; off; off >>= 1) {
        p0 += __shfl_down_sync(0xFFFFFFFFu, p0, off);
        p1 += __shfl_down_sync(0xFFFFFFFFu, p1, off);
    }
    if (lane == 0) {
        out[warp*2 + 0] = p0 + bclf[0];
        out[warp*2 + 1] = p1 + bclf[1];
    }
}

// ---------------- launch ----------------------------------------------------------
extern "C" void kernel_launch(void* const* d_in, const int* in_sizes, int n_in,
                              void* d_out, int out_size) {
    const float* feat   = (const float*)d_in[0];
    const float* edge_w = (const float*)d_in[1];
    const float* W1     = (const float*)d_in[2];
    const float* Wc1    = (const float*)d_in[3];
    const float* W2     = (const float*)d_in[4];
    const float* Wc2    = (const float*)d_in[5];
    const float* Wclf   = (const float*)d_in[6];
    const float* bclf   = (const float*)d_in[7];
    const int*   esrc   = (const int*)d_in[8];
    const int*   edst   = (const int*)d_in[9];
    float* out = (float*)d_out;

    const int g1_smem_bytes = G1_SMEM_FLOATS * sizeof(float);  // 106496
    static bool attr_set = false;          // host-side API config, not device state;
    if (!attr_set) {                       // launched work is identical every call
        cudaFuncSetAttribute(gemm1_kernel,
                             cudaFuncAttributeMaxDynamicSharedMemorySize, g1_smem_bytes);
        attr_set = true;
    }

    // CSR build (shared by both layers)
    zero_counts_kernel<<<(NN+255)/256, 256>>>();
    hist_kernel<<<(TOTE+255)/256, 256>>>(edst);
    scan_kernel<<<1, 1024>>>();
    scatter_kernel<<<(TOTE+255)/256, 256>>>(esrc, edst, edge_w);

    // layer 1
    repack1_kernel<<<(BB*NN*HH+255)/256, 256>>>(W1);
    gemm1_kernel<<<NN/G1_BM, 256, g1_smem_bytes>>>(feat);
    combine1_kernel<<<(NN*HH+255)/256, 256>>>(Wc1);
    agg1_kernel<<<NN/8, 256>>>();

    // layer 2
    repack2_kernel<<<(BB*64*FF+255)/256, 256>>>(W2);
    gemm2_kernel<<<NN/64, 256>>>();
    combine2_kernel<<<(NN*FF+255)/256, 256>>>(Wc2);

    // layer 2 aggregation + classifier fused
    agg2_kernel<<<NN/8, 256>>>(Wclf, bclf, out);
}

// round 16
// speedup vs baseline: 1.3205x; 1.0094x over previous
#include <cuda_runtime.h>
#include <cuda_bf16.h>
#include <stdint.h>
#include <math.h>

// Problem constants
#define NN      8192
#define SS      4
#define BB      2
#define EE      262144          // edges per relation (2^18)
#define TOTE    (SS*EE)         // 1048576 total edges
#define HH      64
#define FF      32
#define CC      2

// ---------------- device scratch (statically reserved; no runtime alloc) ---------
__device__ float g_Wcat1h[NN*128];                // 4 MB   [k][b*64+h], tf32 hi
__device__ float g_Wcat1l[NN*128];                // 4 MB   tf32 lo residual
__device__ float g_U1   [NN*128];                 // 4 MB   feat @ Wcat1
__device__ float g_sup1 [SS*NN*HH];               // 8 MB   [s][n][64]
__device__ float g_X1   [NN*HH];                  // 2 MB
__device__ float g_Wcat2[64*64];                  // [k][b*32+f]
__device__ float g_U2   [NN*64];                  // 2 MB
__device__ float g_sup2 [SS*NN*FF];               // 4 MB
__device__ int   g_deg  [NN];
__device__ int   g_rowptr[NN+1];
__device__ int   g_cursor[NN];
__device__ int   g_gidx [TOTE];                   // s*NN + src, sorted by dst
__device__ float g_ew   [TOTE];

__device__ __forceinline__ float to_tf32(float x) {
    float r;
    asm("cvt.rna.tf32.f32 %0, %1;" : "=f"(r) : "f"(x));
    return r;
}
__device__ __forceinline__ void split_tf32(float x, float& h, float& l) {
    h = to_tf32(x);
    l = to_tf32(x - h);
}

// ---------------- CSR construction ----------------------------------------------
__global__ void zero_counts_kernel() {
    int i = blockIdx.x*256 + threadIdx.x;
    if (i < NN) { g_deg[i] = 0; g_cursor[i] = 0; }
}

__global__ void hist_kernel(const int* __restrict__ dst) {
    int i = blockIdx.x*256 + threadIdx.x;
    if (i < TOTE) atomicAdd(&g_deg[dst[i]], 1);
}

// single block: exclusive scan of 8192 degrees
__global__ void scan_kernel() {
    __shared__ int part[1024];
    int t = threadIdx.x;
    int base = t*8;
    int local[8]; int s = 0;
    #pragma unroll
    for (int i=0;i<8;i++){ local[i] = s; s += g_deg[base+i]; }
    part[t] = s;
    __syncthreads();
    for (int off=1; off<1024; off<<=1) {
        int v = (t >= off) ? part[t-off] : 0;
        __syncthreads();
        part[t] += v;
        __syncthreads();
    }
    int pre = (t==0) ? 0 : part[t-1];
    #pragma unroll
    for (int i=0;i<8;i++) g_rowptr[base+i] = pre + local[i];
    if (t == 1023) g_rowptr[NN] = part[1023];
}

__global__ void scatter_kernel(const int* __restrict__ src,
                               const int* __restrict__ dst,
                               const float* __restrict__ w) {
    int i = blockIdx.x*256 + threadIdx.x;
    if (i >= TOTE) return;
    int s = i >> 18;                         // E = 2^18
    int d = dst[i];
    int p = g_rowptr[d] + atomicAdd(&g_cursor[d], 1);
    g_gidx[p] = s*NN + src[i];
    g_ew[p]   = w[i];
}

// ---------------- weight repack: tf32 hi/lo split of B ---------------------------
__global__ void repack1_kernel(const float* __restrict__ W1) {
    int i = blockIdx.x*256 + threadIdx.x;    // over 2*8192*64
    if (i >= BB*NN*HH) return;
    int b = i / (NN*HH);
    int r = i % (NN*HH);
    int k = r / HH, h = r % HH;
    float hi, lo;
    split_tf32(W1[i], hi, lo);
    g_Wcat1h[k*128 + b*64 + h] = hi;
    g_Wcat1l[k*128 + b*64 + h] = lo;
}

__global__ void repack2_kernel(const float* __restrict__ W2) {
    int i = blockIdx.x*256 + threadIdx.x;    // over 2*64*32
    if (i >= BB*64*FF) return;
    int b = i / (64*FF);
    int r = i % (64*FF);
    int k = r / FF, f = r % FF;
    g_Wcat2[k*64 + b*32 + f] = W2[i];
}

// ---------------- GEMM1: feat[8192,8192] @ Wcat1[8192,128], 3-pass tf32 ----------
// acc += Ah*Bh + Al*Bh + Ah*Bl  (drops Al*Bl ~ eps^2)
// Tile: BM=64, BN=128, BK=32. 256 threads = 8 warps (2x4), warp tile 32x32.
// Fragment loads double-buffered in registers: prefetch kc+1 under kc's mmas.
#define G1_BM 64
#define G1_BK 32
#define AS_PAD 36
#define BS_PAD 136
#define AS_STAGE (G1_BM*AS_PAD)     // 2304 floats
#define BS_STAGE (G1_BK*BS_PAD)     // 4352 floats
#define AH_OFF 0
#define AL_OFF (2*AS_STAGE)
#define BH_OFF (4*AS_STAGE)
#define BL_OFF (4*AS_STAGE + 2*BS_STAGE)
#define G1_SMEM_FLOATS (4*AS_STAGE + 4*BS_STAGE)   // 26624 floats = 106496 B

__device__ __forceinline__ void cp_async16(uint32_t smem_addr, const void* gptr) {
    asm volatile("cp.async.cg.shared.global [%0], [%1], 16;\n"
                 :: "r"(smem_addr), "l"(gptr));
}

#define MMA_TF32(ACC, AF, BF)                                              \
    asm volatile(                                                          \
        "mma.sync.aligned.m16n8k8.row.col.f32.tf32.tf32.f32 "              \
        "{%0,%1,%2,%3}, {%4,%5,%6,%7}, {%8,%9}, {%0,%1,%2,%3};"            \
        : "+f"((ACC)[0]), "+f"((ACC)[1]), "+f"((ACC)[2]), "+f"((ACC)[3])   \
        : "r"((AF)[0]), "r"((AF)[1]), "r"((AF)[2]), "r"((AF)[3]),          \
          "r"((BF)[0]), "r"((BF)[1]))

// Load all h/l fragments for k-chunk KC into register buffer BUF.
#define LOAD_FRAGS(BUF, KC) do {                                           \
    _Pragma("unroll")                                                      \
    for (int _i=0;_i<2;_i++) {                                             \
        int _off = (wm*32 + _i*16 + g)*AS_PAD + (KC)*8 + tg;               \
        const float* _ph = Ahc + _off;                                     \
        afh[BUF][_i][0] = __float_as_uint(_ph[0]);                         \
        afh[BUF][_i][1] = __float_as_uint(_ph[8*AS_PAD]);                  \
        afh[BUF][_i][2] = __float_as_uint(_ph[4]);                         \
        afh[BUF][_i][3] = __float_as_uint(_ph[8*AS_PAD + 4]);              \
        const float* _pl = Alc + _off;                                     \
        afl[BUF][_i][0] = __float_as_uint(_pl[0]);                         \
        afl[BUF][_i][1] = __float_as_uint(_pl[8*AS_PAD]);                  \
        afl[BUF][_i][2] = __float_as_uint(_pl[4]);                         \
        afl[BUF][_i][3] = __float_as_uint(_pl[8*AS_PAD + 4]);              \
    }                                                                      \
    _Pragma("unroll")                                                      \
    for (int _j=0;_j<4;_j++) {                                             \
        int _off = ((KC)*8 + tg)*BS_PAD + wn*32 + _j*8 + g;                \
        const float* _ph = Bhc + _off;                                     \
        bfh[BUF][_j][0] = __float_as_uint(_ph[0]);                         \
        bfh[BUF][_j][1] = __float_as_uint(_ph[4*BS_PAD]);                  \
        const float* _pl = Blc + _off;                                     \
        bfl[BUF][_j][0] = __float_as_uint(_pl[0]);                         \
        bfl[BUF][_j][1] = __float_as_uint(_pl[4*BS_PAD]);                  \
    }                                                                      \
} while(0)

__global__ void __launch_bounds__(256, 1)
gemm1_kernel(const float* __restrict__ A) {
    extern __shared__ float sm[];

    const int tid  = threadIdx.x;
    const int warp = tid >> 5;
    const int lane = tid & 31;
    const int wm   = warp >> 2;           // 0..1
    const int wn   = warp & 3;            // 0..3
    const int g    = lane >> 2;           // group 0..7
    const int tg   = lane & 3;            // 0..3
    const int m0   = blockIdx.x * G1_BM;

    // staging maps
    const int arow = tid >> 2;            // 0..63
    const int af4  = tid & 3;             // 0..3  (handles float4 slots af4 and af4+4)
    const float* Arow_base = A + (size_t)(m0 + arow) * NN;

    float acc[2][4][4];
    #pragma unroll
    for (int i=0;i<2;i++)
        #pragma unroll
        for (int j=0;j<4;j++)
            #pragma unroll
            for (int c=0;c<4;c++) acc[i][j][c] = 0.f;

    // ---- prologue: fill stage 0 ----
    {
        float4 va0 = *(const float4*)(Arow_base + af4*4);
        float4 va1 = *(const float4*)(Arow_base + af4*4 + 16);
        float* dh0 = sm + AH_OFF + arow*AS_PAD + af4*4;
        float* dl0 = sm + AL_OFF + arow*AS_PAD + af4*4;
        float h, l;
        split_tf32(va0.x,h,l); dh0[0]=h; dl0[0]=l;
        split_tf32(va0.y,h,l); dh0[1]=h; dl0[1]=l;
        split_tf32(va0.z,h,l); dh0[2]=h; dl0[2]=l;
        split_tf32(va0.w,h,l); dh0[3]=h; dl0[3]=l;
        split_tf32(va1.x,h,l); dh0[16]=h; dl0[16]=l;
        split_tf32(va1.y,h,l); dh0[17]=h; dl0[17]=l;
        split_tf32(va1.z,h,l); dh0[18]=h; dl0[18]=l;
        split_tf32(va1.w,h,l); dh0[19]=h; dl0[19]=l;
        #pragma unroll
        for (int i=0;i<4;i++) {
            int idx = tid + 256*i;          // 0..1023 float4s of B tile
            int br = idx >> 5, q = idx & 31;
            uint32_t dh = (uint32_t)__cvta_generic_to_shared(sm + BH_OFF + br*BS_PAD + q*4);
            cp_async16(dh, g_Wcat1h + (size_t)br*128 + q*4);
            uint32_t dl = (uint32_t)__cvta_generic_to_shared(sm + BL_OFF + br*BS_PAD + q*4);
            cp_async16(dl, g_Wcat1l + (size_t)br*128 + q*4);
        }
        asm volatile("cp.async.commit_group;");
        asm volatile("cp.async.wait_group 0;");
    }
    __syncthreads();

    #pragma unroll 1
    for (int kt = 0; kt < NN; kt += G1_BK) {
        const int s = (kt >> 5) & 1;
        const bool has_next = (kt + G1_BK) < NN;
        float4 pa0, pa1;
        if (has_next) {
            const int knx = kt + G1_BK;
            #pragma unroll
            for (int i=0;i<4;i++) {
                int idx = tid + 256*i;
                int br = idx >> 5, q = idx & 31;
                uint32_t dh = (uint32_t)__cvta_generic_to_shared(
                    sm + BH_OFF + (s^1)*BS_STAGE + br*BS_PAD + q*4);
                cp_async16(dh, g_Wcat1h + (size_t)(knx + br)*128 + q*4);
                uint32_t dl = (uint32_t)__cvta_generic_to_shared(
                    sm + BL_OFF + (s^1)*BS_STAGE + br*BS_PAD + q*4);
                cp_async16(dl, g_Wcat1l + (size_t)(knx + br)*128 + q*4);
            }
            asm volatile("cp.async.commit_group;");
            pa0 = *(const float4*)(Arow_base + knx + af4*4);
            pa1 = *(const float4*)(Arow_base + knx + af4*4 + 16);
        }

        // ---- compute on stage s, fragment double-buffered over kc ----
        const float* Ahc = sm + AH_OFF + s*AS_STAGE;
        const float* Alc = sm + AL_OFF + s*AS_STAGE;
        const float* Bhc = sm + BH_OFF + s*BS_STAGE;
        const float* Blc = sm + BL_OFF + s*BS_STAGE;

        uint32_t afh[2][2][4], afl[2][2][4];
        uint32_t bfh[2][4][2], bfl[2][4][2];
        LOAD_FRAGS(0, 0);
        #pragma unroll
        for (int kc = 0; kc < 4; kc++) {
            const int cur = kc & 1;
            if (kc < 3) {
                const int nxt = cur ^ 1;
                LOAD_FRAGS(nxt, kc + 1);
            }
            #pragma unroll
            for (int i=0;i<2;i++)
                #pragma unroll
                for (int j=0;j<4;j++) {
                    MMA_TF32(acc[i][j], afh[cur][i], bfh[cur][j]);   // Ah*Bh
                    MMA_TF32(acc[i][j], afl[cur][i], bfh[cur][j]);   // Al*Bh
                    MMA_TF32(acc[i][j], afh[cur][i], bfl[cur][j]);   // Ah*Bl
                }
        }

        if (has_next) {
            float* dh0 = sm + AH_OFF + (s^1)*AS_STAGE + arow*AS_PAD + af4*4;
            float* dl0 = sm + AL_OFF + (s^1)*AS_STAGE + arow*AS_PAD + af4*4;
            float h, l;
            split_tf32(pa0.x,h,l); dh0[0]=h; dl0[0]=l;
            split_tf32(pa0.y,h,l); dh0[1]=h; dl0[1]=l;
            split_tf32(pa0.z,h,l); dh0[2]=h; dl0[2]=l;
            split_tf32(pa0.w,h,l); dh0[3]=h; dl0[3]=l;
            split_tf32(pa1.x,h,l); dh0[16]=h; dl0[16]=l;
            split_tf32(pa1.y,h,l); dh0[17]=h; dl0[17]=l;
            split_tf32(pa1.z,h,l); dh0[18]=h; dl0[18]=l;
            split_tf32(pa1.w,h,l); dh0[19]=h; dl0[19]=l;
            asm volatile("cp.async.wait_group 0;");
        }
        __syncthreads();
    }

    // ---- writeback ----
    #pragma unroll
    for (int i=0;i<2;i++) {
        int row = m0 + wm*32 + i*16 + g;
        #pragma unroll
        for (int j=0;j<4;j++) {
            int col = wn*32 + j*8 + 2*tg;
            *(float2*)(g_U1 + (size_t)row*128 + col) =
                make_float2(acc[i][j][0], acc[i][j][1]);
            *(float2*)(g_U1 + (size_t)(row+8)*128 + col) =
                make_float2(acc[i][j][2], acc[i][j][3]);
        }
    }
}

// ---------------- basis combine (layer 1) ----------------------------------------
// sup1[s][n][h] = Wc1[s,0]*U[n][h] + Wc1[s,1]*U[n][64+h]
__global__ void combine1_kernel(const float* __restrict__ Wc1) {
    int i = blockIdx.x*256 + threadIdx.x;   // over 8192*64
    if (i >= NN*HH) return;
    int n = i >> 6, h = i & 63;
    float u0 = g_U1[n*128 + h];
    float u1 = g_U1[n*128 + 64 + h];
    #pragma unroll
    for (int s=0;s<4;s++)
        g_sup1[((size_t)s*NN + n)*HH + h] = Wc1[2*s]*u0 + Wc1[2*s+1]*u1;
}

// ---------------- aggregation layer 1: warp per dst, 64-wide, tanh ----------------
__global__ void agg1_kernel() {
    int warp = (blockIdx.x*blockDim.x + threadIdx.x) >> 5;
    int lane = threadIdx.x & 31;
    if (warp >= NN) return;
    int beg = g_rowptr[warp], end = g_rowptr[warp+1];
    float ax = 0.f, ay = 0.f;
    int e = beg;
    for (; e + 3 < end; e += 4) {
        int   g0 = g_gidx[e],   g1 = g_gidx[e+1], g2 = g_gidx[e+2], g3 = g_gidx[e+3];
        float w0 = g_ew[e],     w1 = g_ew[e+1],   w2 = g_ew[e+2],   w3 = g_ew[e+3];
        float2 v0 = *(const float2*)(g_sup1 + (size_t)g0*64 + 2*lane);
        float2 v1 = *(const float2*)(g_sup1 + (size_t)g1*64 + 2*lane);
        float2 v2 = *(const float2*)(g_sup1 + (size_t)g2*64 + 2*lane);
        float2 v3 = *(const float2*)(g_sup1 + (size_t)g3*64 + 2*lane);
        ax += w0*v0.x + w1*v1.x + w2*v2.x + w3*v3.x;
        ay += w0*v0.y + w1*v1.y + w2*v2.y + w3*v3.y;
    }
    for (; e < end; e++) {
        int g = g_gidx[e]; float w = g_ew[e];
        float2 v = *(const float2*)(g_sup1 + (size_t)g*64 + 2*lane);
        ax += w*v.x; ay += w*v.y;
    }
    float2 o; o.x = tanhf(ax); o.y = tanhf(ay);
    *(float2*)(g_X1 + (size_t)warp*64 + 2*lane) = o;
}

// ---------------- GEMM2: X1[8192,64] @ Wcat2[64,64] -------------------------------
__global__ void gemm2_kernel() {
    __shared__ float Ws[64][64];
    __shared__ float Xs[64][65];
    int tid = threadIdx.x;
    for (int i = tid; i < 4096; i += 256) Ws[i>>6][i&63] = g_Wcat2[i];
    int row0 = blockIdx.x * 64;
    for (int i = tid; i < 4096; i += 256)
        Xs[i>>6][i&63] = g_X1[(size_t)(row0 + (i>>6))*64 + (i&63)];
    __syncthreads();
    int r  = tid >> 2;
    int c0 = (tid & 3) * 16;
    float acc[16];
    #pragma unroll
    for (int j=0;j<16;j++) acc[j] = 0.f;
    #pragma unroll 8
    for (int k=0;k<64;k++) {
        float x = Xs[r][k];
        #pragma unroll
        for (int j=0;j<16;j++) acc[j] += x * Ws[k][c0+j];
    }
    #pragma unroll
    for (int j=0;j<16;j++) g_U2[(size_t)(row0+r)*64 + c0 + j] = acc[j];
}

// ---------------- basis combine layer 2 ------------------------------------------
__global__ void combine2_kernel(const float* __restrict__ Wc2) {
    int i = blockIdx.x*256 + threadIdx.x;   // over 8192*32
    if (i >= NN*FF) return;
    int n = i >> 5, f = i & 31;
    float u0 = g_U2[n*64 + f];
    float u1 = g_U2[n*64 + 32 + f];
    #pragma unroll
    for (int s=0;s<4;s++)
        g_sup2[((size_t)s*NN + n)*FF + f] = Wc2[2*s]*u0 + Wc2[2*s+1]*u1;
}

// ---------------- aggregation layer 2 + tanh + classifier -------------------------
__global__ void agg2_kernel(const float* __restrict__ Wclf,
                            const float* __restrict__ bclf,
                            float* __restrict__ out) {
    int warp = (blockIdx.x*blockDim.x + threadIdx.x) >> 5;
    int lane = threadIdx.x & 31;
    if (warp >= NN) return;
    int beg = g_rowptr[warp], end = g_rowptr[warp+1];
    float acc = 0.f;
    int e = beg;
    for (; e + 3 < end; e += 4) {
        int   g0 = g_gidx[e],   g1 = g_gidx[e+1], g2 = g_gidx[e+2], g3 = g_gidx[e+3];
        float w0 = g_ew[e],     w1 = g_ew[e+1],   w2 = g_ew[e+2],   w3 = g_ew[e+3];
        acc += w0 * g_sup2[(size_t)g0*32 + lane];
        acc += w1 * g_sup2[(size_t)g1*32 + lane];
        acc += w2 * g_sup2[(size_t)g2*32 + lane];
        acc += w3 * g_sup2[(size_t)g3*32 + lane];
    }
    for (; e < end; e++)
        acc += g_ew[e] * g_sup2[(size_t)g_gidx[e]*32 + lane];
    float x = tanhf(acc);
    float p0 = x * Wclf[lane*2 + 0];
    float p1 = x * Wclf[lane*2 + 1];
    #pragma unroll
    for (int off=16; off; off >>= 1) {
        p0 += __shfl_down_sync(0xFFFFFFFFu, p0, off);
        p1 += __shfl_down_sync(0xFFFFFFFFu, p1, off);
    }
    if (lane == 0) {
        out[warp*2 + 0] = p0 + bclf[0];
        out[warp*2 + 1] = p1 + bclf[1];
    }
}

// ---------------- launch ----------------------------------------------------------
extern "C" void kernel_launch(void* const* d_in, const int* in_sizes, int n_in,
                              void* d_out, int out_size) {
    const float* feat   = (const float*)d_in[0];
    const float* edge_w = (const float*)d_in[1];
    const float* W1     = (const float*)d_in[2];
    const float* Wc1    = (const float*)d_in[3];
    const float* W2     = (const float*)d_in[4];
    const float* Wc2    = (const float*)d_in[5];
    const float* Wclf   = (const float*)d_in[6];
    const float* bclf   = (const float*)d_in[7];
    const int*   esrc   = (const int*)d_in[8];
    const int*   edst   = (const int*)d_in[9];
    float* out = (float*)d_out;

    const int g1_smem_bytes = G1_SMEM_FLOATS * sizeof(float);  // 106496
    static bool attr_set = false;          // host-side API config, not device state;
    if (!attr_set) {                       // launched work is identical every call
        cudaFuncSetAttribute(gemm1_kernel,
                             cudaFuncAttributeMaxDynamicSharedMemorySize, g1_smem_bytes);
        attr_set = true;
    }

    // CSR build (shared by both layers)
    zero_counts_kernel<<<(NN+255)/256, 256>>>();
    hist_kernel<<<(TOTE+255)/256, 256>>>(edst);
    scan_kernel<<<1, 1024>>>();
    scatter_kernel<<<(TOTE+255)/256, 256>>>(esrc, edst, edge_w);

    // layer 1
    repack1_kernel<<<(BB*NN*HH+255)/256, 256>>>(W1);
    gemm1_kernel<<<NN/G1_BM, 256, g1_smem_bytes>>>(feat);
    combine1_kernel<<<(NN*HH+255)/256, 256>>>(Wc1);
    agg1_kernel<<<NN/8, 256>>>();

    // layer 2
    repack2_kernel<<<(BB*64*FF+255)/256, 256>>>(W2);
    gemm2_kernel<<<NN/64, 256>>>();
    combine2_kernel<<<(NN*FF+255)/256, 256>>>(Wc2);

    // layer 2 aggregation + classifier fused
    agg2_kernel<<<NN/8, 256>>>(Wclf, bclf, out);
}